// round 13
// baseline (speedup 1.0000x reference)
#include <cuda_runtime.h>
#include <cuda_fp16.h>
#include <math_constants.h>
#include <cstdint>

// Problem constants
#define BB 8
#define TT 8192
#define DD 512
#define QQ 1024
#define CC 4096
#define MM (BB * TT)   // 65536

typedef __half h16;

// ---------------------------------------------------------------------------
// Scratch (__device__ globals; allocation-free rule)
// ---------------------------------------------------------------------------
__device__ __align__(16) h16 g_x_hi[(size_t)MM * DD];
__device__ __align__(16) h16 g_x_lo[(size_t)MM * DD];
__device__ __align__(16) h16 g_w2t_hi[(size_t)CC * DD];   // W2^T [C][D]
__device__ __align__(16) h16 g_w2t_lo[(size_t)CC * DD];
__device__ __align__(16) h16 g_ew_hi[(size_t)QQ * DD];
__device__ __align__(16) h16 g_sc[(size_t)MM * CC];       // approx scores (512 MB)
__device__ float g_csq[CC];
__device__ unsigned long long g_key[MM];

// ---------------------------------------------------------------------------
// PTX helpers
// ---------------------------------------------------------------------------
__device__ __forceinline__ uint32_t smem_u32(const void* p) {
    uint32_t a;
    asm("{ .reg .u64 t; cvta.to.shared.u64 t, %1; cvt.u32.u64 %0, t; }"
        : "=r"(a) : "l"(p));
    return a;
}
__device__ __forceinline__ void cp16(uint32_t dst, const void* src) {
    asm volatile("cp.async.cg.shared.global [%0], [%1], 16;" :: "r"(dst), "l"(src));
}
#define CP_COMMIT() asm volatile("cp.async.commit_group;")
#define CP_WAIT1()  asm volatile("cp.async.wait_group 1;")
#define CP_WAIT0()  asm volatile("cp.async.wait_group 0;")

__device__ __forceinline__ void ldmx4(uint32_t* r, uint32_t addr) {
    asm volatile("ldmatrix.sync.aligned.m8n8.x4.shared.b16 {%0,%1,%2,%3}, [%4];"
                 : "=r"(r[0]), "=r"(r[1]), "=r"(r[2]), "=r"(r[3]) : "r"(addr));
}
__device__ __forceinline__ void mma16816_f32(float* d, const uint32_t* a,
                                             uint32_t b0, uint32_t b1) {
    asm volatile("mma.sync.aligned.m16n8k16.row.col.f32.f16.f16.f32 "
                 "{%0,%1,%2,%3}, {%4,%5,%6,%7}, {%8,%9}, {%0,%1,%2,%3};"
                 : "+f"(d[0]), "+f"(d[1]), "+f"(d[2]), "+f"(d[3])
                 : "r"(a[0]), "r"(a[1]), "r"(a[2]), "r"(a[3]), "r"(b0), "r"(b1));
}
__device__ __forceinline__ void mma16816_f16(uint32_t* d, const uint32_t* a,
                                             uint32_t b0, uint32_t b1) {
    asm volatile("mma.sync.aligned.m16n8k16.row.col.f16.f16.f16.f16 "
                 "{%0,%1}, {%2,%3,%4,%5}, {%6,%7}, {%0,%1};"
                 : "+r"(d[0]), "+r"(d[1])
                 : "r"(a[0]), "r"(a[1]), "r"(a[2]), "r"(a[3]), "r"(b0), "r"(b1));
}

// float <-> order-preserving uint32 (ascending)
__device__ __forceinline__ uint32_t ford(float s) {
    uint32_t b = __float_as_uint(s);
    return (b & 0x80000000u) ? ~b : (b | 0x80000000u);
}
__device__ __forceinline__ float unford(uint32_t f) {
    uint32_t b = (f & 0x80000000u) ? (f & 0x7FFFFFFFu) : ~f;
    return __uint_as_float(b);
}

// ---------------------------------------------------------------------------
// Screen GEMM: BM=BN=128, BK=64, f16 accum, 1-pass hi.
// 128 threads, 2x2 warp grid, 64x64 warp tile: 8 LDSM feed 32 MMAs per ks
// (33% less smem traffic per MAC vs 8-warp layout). NSTAGE=2, stage=32KB
// -> 64KB smem -> 3 CTAs/SM @ 128 thr (regs fit under 170).
// score = csq[c] - 2*dot; fp16 score store + per-row packed atomicMin.
// ---------------------------------------------------------------------------
#define SCR_TA  0
#define SCR_TB  16384
#define SCR_STG 32768
#define SMEM_SCREEN (2 * SCR_STG)

__global__ __launch_bounds__(128, 3) void hgemm_screen(
    const h16* __restrict__ A, const h16* __restrict__ B, int K)
{
    extern __shared__ __align__(1024) char smem[];
    const uint32_t sb = smem_u32(smem);
    const int tid  = threadIdx.x;
    const int lane = tid & 31;
    const int wid  = tid >> 5;      // 0..3
    const int wy   = wid >> 1;      // 0..1  (64-row half)
    const int wx   = wid & 1;       // 0..1  (64-col half)
    const size_t bm = (size_t)blockIdx.y * 128;
    const size_t bn = (size_t)blockIdx.x * 128;

    uint32_t acc[4][8][2];
    #pragma unroll
    for (int i = 0; i < 4; i++)
        #pragma unroll
        for (int j = 0; j < 8; j++) { acc[i][j][0] = 0u; acc[i][j][1] = 0u; }

    // loaders: one thread per row for A and B (128 threads, 128 rows each)
    const uint32_t swr = (uint32_t)((tid & 7) << 4);
    const char* pA = (const char*)(A + (bm + tid) * (size_t)K);
    const char* pB = (const char*)(B + (bn + tid) * (size_t)K);
    const int nch = K >> 6;

    auto load_stage = [&](int s, int kc) {
        uint32_t st = sb + (uint32_t)s * SCR_STG;
        int kbyte0 = kc << 7;
        #pragma unroll
        for (int i = 0; i < 8; i++) {
            uint32_t ko = (uint32_t)(i * 16);
            uint32_t d  = (uint32_t)(tid * 128) + (ko ^ swr);
            cp16(st + SCR_TA + d, pA + kbyte0 + ko);
            cp16(st + SCR_TB + d, pB + kbyte0 + ko);
        }
        CP_COMMIT();
    };

    // fragment address precompute
    const int rl  = lane & 15;
    const uint32_t kbh = (uint32_t)((lane >> 4) << 4);
    uint32_t a_base[4], a_swz[4], b_base[4], b_swz[4];
    #pragma unroll
    for (int mf = 0; mf < 4; mf++) {
        int r = wy * 64 + mf * 16 + rl;
        a_base[mf] = (uint32_t)(r * 128);
        a_swz[mf]  = (uint32_t)((r & 7) << 4);
    }
    #pragma unroll
    for (int np = 0; np < 4; np++) {
        int n = wx * 64 + np * 16 + rl;
        b_base[np] = (uint32_t)(n * 128);
        b_swz[np]  = (uint32_t)((n & 7) << 4);
    }

    auto compute_stage = [&](int s) {
        uint32_t base = sb + (uint32_t)s * SCR_STG;
        uint32_t aP = base + SCR_TA, bP = base + SCR_TB;
        #pragma unroll
        for (int ks = 0; ks < 4; ks++) {
            uint32_t kb = (uint32_t)(ks * 32) + kbh;
            uint32_t a_h[4][4], b_h[4][4];
            #pragma unroll
            for (int mf = 0; mf < 4; mf++)
                ldmx4(a_h[mf], aP + a_base[mf] + (kb ^ a_swz[mf]));
            #pragma unroll
            for (int np = 0; np < 4; np++)
                ldmx4(b_h[np], bP + b_base[np] + (kb ^ b_swz[np]));
            #pragma unroll
            for (int mf = 0; mf < 4; mf++)
                #pragma unroll
                for (int nf = 0; nf < 8; nf++) {
                    int p = nf >> 1, q = nf & 1;
                    mma16816_f16(acc[mf][nf], a_h[mf], b_h[p][q], b_h[p][q + 2]);
                }
        }
    };

    // 2-stage pipelined main loop
    load_stage(0, 0);
    for (int kc = 0; kc < nch; kc++) {
        if (kc + 1 < nch) load_stage((kc + 1) & 1, kc + 1);
        if (kc + 1 < nch) { CP_WAIT1(); } else { CP_WAIT0(); }
        __syncthreads();
        compute_stage(kc & 1);
        __syncthreads();
    }

    // epilogue (R7-proven pattern, nf widened to 8, wx in {0,1})
    const int qrow = lane >> 2;
    const int c2   = 2 * (lane & 3);
    #pragma unroll
    for (int mf = 0; mf < 4; mf++) {
        #pragma unroll
        for (int sub = 0; sub < 2; sub++) {
            size_t row = bm + (size_t)(wy * 64 + mf * 16 + sub * 8 + qrow);
            unsigned long long best = 0xFFFFFFFFFFFFFFFFull;
            #pragma unroll
            for (int nf = 0; nf < 8; nf++) {
                int col = (int)bn + wx * 64 + nf * 8 + c2;
                __half2 d2 = *(__half2*)&acc[mf][nf][sub];
                float s0 = g_csq[col]     - 2.0f * __half2float(__low2half(d2));
                float s1 = g_csq[col + 1] - 2.0f * __half2float(__high2half(d2));
                __half2 hp = __floats2half2_rn(s0, s1);
                uint32_t u; *(__half2*)&u = hp;
                __stcs((uint32_t*)(g_sc + row * CC + col), u);
                unsigned long long k0 =
                    ((unsigned long long)ford(s0) << 32) | (uint32_t)col;
                unsigned long long k1 =
                    ((unsigned long long)ford(s1) << 32) | (uint32_t)(col + 1);
                if (k0 < best) best = k0;
                if (k1 < best) best = k1;
            }
            unsigned long long o;
            o = __shfl_down_sync(0xFFFFFFFFu, best, 2);
            if (o < best) best = o;
            o = __shfl_down_sync(0xFFFFFFFFu, best, 1);
            if (o < best) best = o;
            if ((lane & 3) == 0) atomicMin(&g_key[row], best);
        }
    }
}

// ---------------------------------------------------------------------------
// Encoder GEMM (unchanged, R10/R11-proven): BM=BN=128, BK=64, fp32 accum,
// NSTAGE=3, 2 CTAs/SM.
// ---------------------------------------------------------------------------
#define T_A    0
#define T_B    16384
#define STG1   32768
#define NSTAGE_ENC 3
#define SMEM_ENC (NSTAGE_ENC * STG1)

__global__ __launch_bounds__(256, 2) void hgemm_enc(
    const h16* __restrict__ A, const h16* __restrict__ B,
    int K, int Ntot, const float* __restrict__ bias, float* __restrict__ outf)
{
    extern __shared__ __align__(1024) char smem[];
    const uint32_t sb = smem_u32(smem);
    const int tid  = threadIdx.x;
    const int lane = tid & 31;
    const int wid  = tid >> 5;
    const int wy   = wid >> 2;
    const int wx   = wid & 3;
    const size_t bm = (size_t)blockIdx.y * 128;
    const size_t bn = (size_t)blockIdx.x * 128;

    const int lrow  = tid >> 1;
    const int lhalf = tid & 1;
    const uint32_t swr   = (uint32_t)((lrow & 7) << 4);
    const uint32_t rbase = (uint32_t)(lrow * 128);
    const char* pA = (const char*)(A + (bm + lrow) * (size_t)K);
    const char* pB = (const char*)(B + (bn + lrow) * (size_t)K);
    const int nch = K >> 6;

    auto load_stage = [&](int s, int kc) {
        uint32_t st = sb + (uint32_t)s * STG1;
        int kbyte0 = kc << 7;
        #pragma unroll
        for (int i = 0; i < 4; i++) {
            uint32_t ko = (uint32_t)(lhalf * 64 + i * 16);
            uint32_t d  = rbase + (ko ^ swr);
            cp16(st + T_A + d, pA + kbyte0 + ko);
            cp16(st + T_B + d, pB + kbyte0 + ko);
        }
        CP_COMMIT();
    };

    const int rl  = lane & 15;
    const uint32_t kbh = (uint32_t)((lane >> 4) << 4);
    uint32_t a_base[4], a_swz[4], b_base[2], b_swz[2];
    #pragma unroll
    for (int mf = 0; mf < 4; mf++) {
        int r = wy * 64 + mf * 16 + rl;
        a_base[mf] = (uint32_t)(r * 128);
        a_swz[mf]  = (uint32_t)((r & 7) << 4);
    }
    #pragma unroll
    for (int np = 0; np < 2; np++) {
        int n = wx * 32 + np * 16 + rl;
        b_base[np] = (uint32_t)(n * 128);
        b_swz[np]  = (uint32_t)((n & 7) << 4);
    }

    float acc[4][4][4];
    #pragma unroll
    for (int i = 0; i < 4; i++)
        #pragma unroll
        for (int j = 0; j < 4; j++)
            #pragma unroll
            for (int k = 0; k < 4; k++) acc[i][j][k] = 0.f;

    auto compute_stage = [&](int s) {
        uint32_t base = sb + (uint32_t)s * STG1;
        uint32_t aP = base + T_A, bP = base + T_B;
        #pragma unroll
        for (int ks = 0; ks < 4; ks++) {
            uint32_t kb = (uint32_t)(ks * 32) + kbh;
            uint32_t a_h[4][4], b_h[2][4];
            #pragma unroll
            for (int mf = 0; mf < 4; mf++)
                ldmx4(a_h[mf], aP + a_base[mf] + (kb ^ a_swz[mf]));
            #pragma unroll
            for (int np = 0; np < 2; np++)
                ldmx4(b_h[np], bP + b_base[np] + (kb ^ b_swz[np]));
            #pragma unroll
            for (int mf = 0; mf < 4; mf++)
                #pragma unroll
                for (int nf = 0; nf < 4; nf++) {
                    int p = nf >> 1, q = nf & 1;
                    mma16816_f32(acc[mf][nf], a_h[mf], b_h[p][q], b_h[p][q + 2]);
                }
        }
    };

    load_stage(0, 0);
    if (nch > 1) load_stage(1, 1);
    int sidx = 0;
    for (int kc = 0; kc < nch; kc++) {
        if (kc + 1 < nch) { CP_WAIT1(); } else { CP_WAIT0(); }
        __syncthreads();
        if (kc + 2 < nch) {
            int s2 = sidx + 2; if (s2 >= NSTAGE_ENC) s2 -= NSTAGE_ENC;
            load_stage(s2, kc + 2);
        }
        compute_stage(sidx);
        if (++sidx == NSTAGE_ENC) sidx = 0;
    }

    const int qrow = lane >> 2;
    const int c2   = 2 * (lane & 3);
    #pragma unroll
    for (int mf = 0; mf < 4; mf++) {
        size_t r0 = bm + (size_t)(wy * 64 + mf * 16 + qrow);
        #pragma unroll
        for (int nf = 0; nf < 4; nf++) {
            size_t col = bn + (size_t)(wx * 32 + nf * 8 + c2);
            float b0 = bias[col], b1 = bias[col + 1];
            #pragma unroll
            for (int sub = 0; sub < 2; sub++) {
                size_t r = r0 + sub * 8;
                float2 o;
                o.x = acc[mf][nf][sub * 2 + 0] + b0;
                o.y = acc[mf][nf][sub * 2 + 1] + b1;
                *(float2*)(outf + r * Ntot + col) = o;
            }
        }
    }
}

// ---------------------------------------------------------------------------
// Refine (R7-proven): streaming uint4 scan; candidates within MARGIN of the
// screen's approx min; exact fp32 recompute; low-index tie break.
// ---------------------------------------------------------------------------
#define MARGIN 8.0f

__global__ __launch_bounds__(256) void refine_kernel(float* __restrict__ labels) {
    int warp = blockIdx.x * 8 + (threadIdx.x >> 5);
    int lane = threadIdx.x & 31;
    size_t row = (size_t)warp;

    float amin   = unford((uint32_t)(g_key[row] >> 32));
    float thresh = amin + MARGIN;
    __half hthr  = __float2half_ru(thresh);

    const h16* sr = g_sc + row * CC;
    float best = CUDART_INF_F;
    int bestc = 0;

    for (int base = 0; base < CC; base += 256) {
        uint4 v = *(const uint4*)(sr + base + lane * 8);
        __half2 p[4];
        p[0] = *(__half2*)&v.x; p[1] = *(__half2*)&v.y;
        p[2] = *(__half2*)&v.z; p[3] = *(__half2*)&v.w;
        __half2 mn2 = __hmin2(__hmin2(p[0], p[1]), __hmin2(p[2], p[3]));
        __half mn = __hmin(__low2half(mn2), __high2half(mn2));
        uint32_t mask = __ballot_sync(0xFFFFFFFFu, __hle(mn, hthr));
        while (mask) {
            int bit = __ffs(mask) - 1;
            mask &= mask - 1;
            #pragma unroll
            for (int j = 0; j < 8; j++) {
                float sv = __half2float(__shfl_sync(0xFFFFFFFFu,
                             ((const __half*)p)[j], bit));
                if (sv > thresh) continue;
                int c = base + bit * 8 + j;
                const h16* xh = g_x_hi + row * DD;
                const h16* xl = g_x_lo + row * DD;
                const h16* wh = g_w2t_hi + (size_t)c * DD;
                const h16* wl = g_w2t_lo + (size_t)c * DD;
                float dot = 0.f;
                #pragma unroll
                for (int jj = 0; jj < 16; jj++) {
                    int d = lane + 32 * jj;
                    float a = __half2float(xh[d]) + __half2float(xl[d]);
                    float b = __half2float(wh[d]) + __half2float(wl[d]);
                    dot = fmaf(a, b, dot);
                }
                #pragma unroll
                for (int off = 16; off > 0; off >>= 1)
                    dot += __shfl_down_sync(0xFFFFFFFFu, dot, off);
                if (lane == 0) {
                    float sc = g_csq[c] - 2.0f * dot;
                    if (sc < best || (sc == best && c < bestc)) { best = sc; bestc = c; }
                }
            }
        }
    }
    if (lane == 0) labels[row] = (float)bestc;
}

// ---------------------------------------------------------------------------
// W2^T precompute + fused csq.
// ---------------------------------------------------------------------------
__global__ __launch_bounds__(256) void w2t_kernel(const float* __restrict__ projw,
                                                  const float* __restrict__ cb) {
    __shared__ __align__(16) float As[8][128];
    __shared__ __align__(16) float Bs[8][128];
    __shared__ float cred[2][128];

    int tid = threadIdx.x;
    int c0 = blockIdx.x * 128;
    int d0 = blockIdx.y * 128;
    int lr = tid >> 5, lc = (tid & 31) * 4;
    int ty = tid >> 4, tx = tid & 15;

    int qcol = tid & 127;
    int qgrp = tid >> 7;
    float csum = 0.f;

    float acc[8][8];
    #pragma unroll
    for (int i = 0; i < 8; i++)
        #pragma unroll
        for (int j = 0; j < 8; j++) acc[i][j] = 0.f;

    for (int k0 = 0; k0 < QQ; k0 += 8) {
        *(float4*)&As[lr][lc] = *(const float4*)(cb + (size_t)(k0 + lr) * CC + c0 + lc);
        *(float4*)&Bs[lr][lc] = *(const float4*)(projw + (size_t)(k0 + lr) * DD + d0 + lc);
        __syncthreads();

        if (d0 == 0) {
            #pragma unroll
            for (int r = 0; r < 4; r++) {
                float v = As[qgrp * 4 + r][qcol];
                csum = fmaf(v, v, csum);
            }
        }

        #pragma unroll
        for (int k = 0; k < 8; k++) {
            float ar[8], br[8];
            float4 a0 = *(const float4*)&As[k][ty * 8];
            float4 a1 = *(const float4*)&As[k][ty * 8 + 4];
            float4 b0 = *(const float4*)&Bs[k][tx * 8];
            float4 b1 = *(const float4*)&Bs[k][tx * 8 + 4];
            ar[0]=a0.x; ar[1]=a0.y; ar[2]=a0.z; ar[3]=a0.w;
            ar[4]=a1.x; ar[5]=a1.y; ar[6]=a1.z; ar[7]=a1.w;
            br[0]=b0.x; br[1]=b0.y; br[2]=b0.z; br[3]=b0.w;
            br[4]=b1.x; br[5]=b1.y; br[6]=b1.z; br[7]=b1.w;
            #pragma unroll
            for (int i = 0; i < 8; i++)
                #pragma unroll
                for (int j = 0; j < 8; j++)
                    acc[i][j] = fmaf(ar[i], br[j], acc[i][j]);
        }
        __syncthreads();
    }

    if (d0 == 0) {
        cred[qgrp][qcol] = csum;
        __syncthreads();
        if (tid < 128) g_csq[c0 + tid] = cred[0][tid] + cred[1][tid];
    }

    #pragma unroll
    for (int i = 0; i < 8; i++) {
        size_t rowo = (size_t)(c0 + ty * 8 + i) * DD + d0 + tx * 8;
        #pragma unroll
        for (int j = 0; j < 8; j++) {
            float v = acc[i][j];
            h16 h = __float2half(v);
            g_w2t_hi[rowo + j] = h;
            g_w2t_lo[rowo + j] = __float2half(v - __half2float(h));
        }
    }
}

// ---------------------------------------------------------------------------
// LayerNorm over D=512, writes fp16 hi/lo split + inits g_key for its row.
// ---------------------------------------------------------------------------
__global__ __launch_bounds__(256) void ln_kernel(const float* __restrict__ x,
                                                 const float* __restrict__ gamma,
                                                 const float* __restrict__ beta) {
    int r = blockIdx.x;
    const float* xr = x + (size_t)r * DD;
    int t = threadIdx.x;

    if (t == 0) g_key[r] = 0xFFFFFFFFFFFFFFFFull;

    float v0 = xr[t], v1 = xr[t + 256];
    float s = v0 + v1, ss = v0 * v0 + v1 * v1;
    #pragma unroll
    for (int off = 16; off > 0; off >>= 1) {
        s  += __shfl_down_sync(0xFFFFFFFFu, s,  off);
        ss += __shfl_down_sync(0xFFFFFFFFu, ss, off);
    }
    __shared__ float sh_s[8], sh_ss[8];
    int w = t >> 5, l = t & 31;
    if (l == 0) { sh_s[w] = s; sh_ss[w] = ss; }
    __syncthreads();
    if (t == 0) {
        float S = 0.f, SS = 0.f;
        #pragma unroll
        for (int i = 0; i < 8; i++) { S += sh_s[i]; SS += sh_ss[i]; }
        sh_s[0]  = S * (1.0f / DD);
        sh_ss[0] = SS * (1.0f / DD);
    }
    __syncthreads();
    float mu = sh_s[0];
    float rs = rsqrtf(sh_ss[0] - mu * mu + 1e-5f);

    float y0 = (v0 - mu) * rs * gamma[t]       + beta[t];
    float y1 = (v1 - mu) * rs * gamma[t + 256] + beta[t + 256];

    size_t base = (size_t)r * DD;
    h16 h0 = __float2half(y0), h1 = __float2half(y1);
    g_x_hi[base + t]       = h0;
    g_x_hi[base + t + 256] = h1;
    g_x_lo[base + t]       = __float2half(y0 - __half2float(h0));
    g_x_lo[base + t + 256] = __float2half(y1 - __half2float(h1));
}

// ---------------------------------------------------------------------------
__global__ __launch_bounds__(256) void split_hi_kernel(const float* __restrict__ src,
                                                       h16* __restrict__ hi, int n) {
    int i = blockIdx.x * 256 + threadIdx.x;
    if (i < n) hi[i] = __float2half(src[i]);
}

// ---------------------------------------------------------------------------
extern "C" void kernel_launch(void* const* d_in, const int* in_sizes, int n_in,
                              void* d_out, int out_size) {
    const float* x     = (const float*)d_in[0];
    const float* gamma = (const float*)d_in[1];
    const float* beta  = (const float*)d_in[2];
    const float* projw = (const float*)d_in[3];
    const float* cb    = (const float*)d_in[4];
    const float* encw  = (const float*)d_in[5];
    const float* encb  = (const float*)d_in[6];

    float* out     = (float*)d_out;
    float* enc_out = out;                               // (M, Q) fp32
    float* labels  = out + ((size_t)out_size - MM);     // (M,) as fp32

    h16 *xh, *w2h, *ewh;
    cudaGetSymbolAddress((void**)&xh, g_x_hi);
    cudaGetSymbolAddress((void**)&w2h, g_w2t_hi);
    cudaGetSymbolAddress((void**)&ewh, g_ew_hi);

    cudaFuncSetAttribute(hgemm_enc, cudaFuncAttributeMaxDynamicSharedMemorySize,
                         SMEM_ENC);
    cudaFuncSetAttribute(hgemm_screen, cudaFuncAttributeMaxDynamicSharedMemorySize,
                         SMEM_SCREEN);

    // Launch order keeps hgemm_screen in the ncu capture slot (4th launch).
    // 1) LayerNorm -> fp16 split (+ g_key init)
    ln_kernel<<<MM, 256>>>(x, gamma, beta);

    // 2) fused codebook matrix W2^T (+ csq in d0==0 blocks)
    w2t_kernel<<<dim3(CC / 128, DD / 128), 256>>>(projw, cb);

    // 3) enc weight split
    split_hi_kernel<<<(QQ * DD + 255) / 256, 256>>>(encw, ewh, QQ * DD);

    // 4) label screen (f16-accum, 128 thr / 2x2 warps / 64x64 warp tile)
    dim3 gridx(CC / 128, MM / 128);
    hgemm_screen<<<gridx, 128, SMEM_SCREEN>>>(xh, w2h, DD);

    // 5) encoder GEMM (fp32-accum 1-pass, 3-stage)
    dim3 grid12(QQ / 128, MM / 128);
    hgemm_enc<<<grid12, 256, SMEM_ENC>>>(xh, ewh, DD, QQ, encb, enc_out);

    // 6) exact refinement -> labels
    refine_kernel<<<MM / 8, 256>>>(labels);

    (void)in_sizes; (void)n_in;
}

// round 14
// speedup vs baseline: 1.2444x; 1.2444x over previous
#include <cuda_runtime.h>
#include <cuda_fp16.h>
#include <math_constants.h>
#include <cstdint>

// Problem constants
#define BB 8
#define TT 8192
#define DD 512
#define QQ 1024
#define CC 4096
#define MM (BB * TT)   // 65536

typedef __half h16;

// ---------------------------------------------------------------------------
// Scratch (__device__ globals; allocation-free rule)
// ---------------------------------------------------------------------------
__device__ __align__(16) h16 g_x_hi[(size_t)MM * DD];
__device__ __align__(16) h16 g_x_lo[(size_t)MM * DD];
__device__ __align__(16) h16 g_w2t_hi[(size_t)CC * DD];   // W2^T [C][D]
__device__ __align__(16) h16 g_w2t_lo[(size_t)CC * DD];
__device__ __align__(16) h16 g_ew_hi[(size_t)QQ * DD];
__device__ __align__(16) uint8_t g_sc8[(size_t)MM * CC];  // u8 scores (256 MB)
__device__ float g_csq[CC];
__device__ unsigned long long g_key[MM];

// Score quantization: q = (s - SCQ_OFF) * SCQ_INV, clamped [0,255].
// Covers s in [256, 1276]; s above clamps to 255 (never a candidate).
#define SCQ_OFF 256.0f
#define SCQ_INV 0.25f
#define SCQ_STEP 4.0f

// ---------------------------------------------------------------------------
// PTX helpers
// ---------------------------------------------------------------------------
__device__ __forceinline__ uint32_t smem_u32(const void* p) {
    uint32_t a;
    asm("{ .reg .u64 t; cvta.to.shared.u64 t, %1; cvt.u32.u64 %0, t; }"
        : "=r"(a) : "l"(p));
    return a;
}
__device__ __forceinline__ void cp16(uint32_t dst, const void* src) {
    asm volatile("cp.async.cg.shared.global [%0], [%1], 16;" :: "r"(dst), "l"(src));
}
#define CP_COMMIT() asm volatile("cp.async.commit_group;")
#define CP_WAIT1()  asm volatile("cp.async.wait_group 1;")
#define CP_WAIT0()  asm volatile("cp.async.wait_group 0;")

__device__ __forceinline__ void ldmx4(uint32_t* r, uint32_t addr) {
    asm volatile("ldmatrix.sync.aligned.m8n8.x4.shared.b16 {%0,%1,%2,%3}, [%4];"
                 : "=r"(r[0]), "=r"(r[1]), "=r"(r[2]), "=r"(r[3]) : "r"(addr));
}
__device__ __forceinline__ void mma16816_f32(float* d, const uint32_t* a,
                                             uint32_t b0, uint32_t b1) {
    asm volatile("mma.sync.aligned.m16n8k16.row.col.f32.f16.f16.f32 "
                 "{%0,%1,%2,%3}, {%4,%5,%6,%7}, {%8,%9}, {%0,%1,%2,%3};"
                 : "+f"(d[0]), "+f"(d[1]), "+f"(d[2]), "+f"(d[3])
                 : "r"(a[0]), "r"(a[1]), "r"(a[2]), "r"(a[3]), "r"(b0), "r"(b1));
}
__device__ __forceinline__ void mma16816_f16(uint32_t* d, const uint32_t* a,
                                             uint32_t b0, uint32_t b1) {
    asm volatile("mma.sync.aligned.m16n8k16.row.col.f16.f16.f16.f16 "
                 "{%0,%1}, {%2,%3,%4,%5}, {%6,%7}, {%0,%1};"
                 : "+r"(d[0]), "+r"(d[1])
                 : "r"(a[0]), "r"(a[1]), "r"(a[2]), "r"(a[3]), "r"(b0), "r"(b1));
}

// float <-> order-preserving uint32 (ascending)
__device__ __forceinline__ uint32_t ford(float s) {
    uint32_t b = __float_as_uint(s);
    return (b & 0x80000000u) ? ~b : (b | 0x80000000u);
}
__device__ __forceinline__ float unford(uint32_t f) {
    uint32_t b = (f & 0x80000000u) ? (f & 0x7FFFFFFFu) : ~f;
    return __uint_as_float(b);
}

// ---------------------------------------------------------------------------
// Screen GEMM (R11-proven mainloop): BM=BN=128, BK=64, f16 accum, 1-pass hi,
// 256 thr (2x4 warps), NSTAGE=2 -> 64KB smem -> 3 CTAs/SM.
// Epilogue: u8-quantized score store + per-row packed fp32 atomicMin.
// ---------------------------------------------------------------------------
#define T_A    0
#define T_B    16384
#define STG1   32768
#define SMEM_SCREEN (2 * STG1)

__global__ __launch_bounds__(256, 3) void hgemm_screen(
    const h16* __restrict__ A, const h16* __restrict__ B, int K)
{
    extern __shared__ __align__(1024) char smem[];
    const uint32_t sb = smem_u32(smem);
    const int tid  = threadIdx.x;
    const int lane = tid & 31;
    const int wid  = tid >> 5;
    const int wy   = wid >> 2;
    const int wx   = wid & 3;
    const size_t bm = (size_t)blockIdx.y * 128;
    const size_t bn = (size_t)blockIdx.x * 128;

    uint32_t acc[4][4][2];
    #pragma unroll
    for (int i = 0; i < 4; i++)
        #pragma unroll
        for (int j = 0; j < 4; j++) { acc[i][j][0] = 0u; acc[i][j][1] = 0u; }

    const int lrow  = tid >> 1;
    const int lhalf = tid & 1;
    const uint32_t swr   = (uint32_t)((lrow & 7) << 4);
    const uint32_t rbase = (uint32_t)(lrow * 128);
    const char* pA = (const char*)(A + (bm + lrow) * (size_t)K);
    const char* pB = (const char*)(B + (bn + lrow) * (size_t)K);
    const int nch = K >> 6;

    auto load_stage = [&](int s, int kc) {
        uint32_t st = sb + (uint32_t)s * STG1;
        int kbyte0 = kc << 7;
        #pragma unroll
        for (int i = 0; i < 4; i++) {
            uint32_t ko = (uint32_t)(lhalf * 64 + i * 16);
            uint32_t d  = rbase + (ko ^ swr);
            cp16(st + T_A + d, pA + kbyte0 + ko);
            cp16(st + T_B + d, pB + kbyte0 + ko);
        }
        CP_COMMIT();
    };

    const int rl  = lane & 15;
    const uint32_t kbh = (uint32_t)((lane >> 4) << 4);
    uint32_t a_base[4], a_swz[4], b_base[2], b_swz[2];
    #pragma unroll
    for (int mf = 0; mf < 4; mf++) {
        int r = wy * 64 + mf * 16 + rl;
        a_base[mf] = (uint32_t)(r * 128);
        a_swz[mf]  = (uint32_t)((r & 7) << 4);
    }
    #pragma unroll
    for (int np = 0; np < 2; np++) {
        int n = wx * 32 + np * 16 + rl;
        b_base[np] = (uint32_t)(n * 128);
        b_swz[np]  = (uint32_t)((n & 7) << 4);
    }

    auto compute_stage = [&](int s) {
        uint32_t base = sb + (uint32_t)s * STG1;
        uint32_t aP = base + T_A, bP = base + T_B;
        #pragma unroll
        for (int ks = 0; ks < 4; ks++) {
            uint32_t kb = (uint32_t)(ks * 32) + kbh;
            uint32_t a_h[4][4], b_h[2][4];
            #pragma unroll
            for (int mf = 0; mf < 4; mf++)
                ldmx4(a_h[mf], aP + a_base[mf] + (kb ^ a_swz[mf]));
            #pragma unroll
            for (int np = 0; np < 2; np++)
                ldmx4(b_h[np], bP + b_base[np] + (kb ^ b_swz[np]));
            #pragma unroll
            for (int mf = 0; mf < 4; mf++)
                #pragma unroll
                for (int nf = 0; nf < 4; nf++) {
                    int p = nf >> 1, q = nf & 1;
                    mma16816_f16(acc[mf][nf], a_h[mf], b_h[p][q], b_h[p][q + 2]);
                }
        }
    };

    // 2-stage pipelined main loop (R11 structure)
    load_stage(0, 0);
    for (int kc = 0; kc < nch; kc++) {
        if (kc + 1 < nch) load_stage((kc + 1) & 1, kc + 1);
        if (kc + 1 < nch) { CP_WAIT1(); } else { CP_WAIT0(); }
        __syncthreads();
        compute_stage(kc & 1);
        __syncthreads();
    }

    // epilogue: u8 score store + packed atomicMin
    const int qrow = lane >> 2;
    const int c2   = 2 * (lane & 3);
    #pragma unroll
    for (int mf = 0; mf < 4; mf++) {
        #pragma unroll
        for (int sub = 0; sub < 2; sub++) {
            size_t row = bm + (size_t)(wy * 64 + mf * 16 + sub * 8 + qrow);
            unsigned long long best = 0xFFFFFFFFFFFFFFFFull;
            #pragma unroll
            for (int nf = 0; nf < 4; nf++) {
                int col = (int)bn + wx * 32 + nf * 8 + c2;
                __half2 d2 = *(__half2*)&acc[mf][nf][sub];
                float s0 = g_csq[col]     - 2.0f * __half2float(__low2half(d2));
                float s1 = g_csq[col + 1] - 2.0f * __half2float(__high2half(d2));
                int q0 = __float2int_rn((s0 - SCQ_OFF) * SCQ_INV);
                int q1 = __float2int_rn((s1 - SCQ_OFF) * SCQ_INV);
                q0 = max(0, min(255, q0));
                q1 = max(0, min(255, q1));
                uint16_t packed = (uint16_t)(q0 | (q1 << 8));
                __stcs((uint16_t*)(g_sc8 + row * CC + col), packed);
                unsigned long long k0 =
                    ((unsigned long long)ford(s0) << 32) | (uint32_t)col;
                unsigned long long k1 =
                    ((unsigned long long)ford(s1) << 32) | (uint32_t)(col + 1);
                if (k0 < best) best = k0;
                if (k1 < best) best = k1;
            }
            unsigned long long o;
            o = __shfl_down_sync(0xFFFFFFFFu, best, 2);
            if (o < best) best = o;
            o = __shfl_down_sync(0xFFFFFFFFu, best, 1);
            if (o < best) best = o;
            if ((lane & 3) == 0) atomicMin(&g_key[row], best);
        }
    }
}

// ---------------------------------------------------------------------------
// Encoder GEMM (unchanged, R10/R11-proven): BM=BN=128, BK=64, fp32 accum,
// NSTAGE=3, 2 CTAs/SM.
// ---------------------------------------------------------------------------
#define NSTAGE_ENC 3
#define SMEM_ENC (NSTAGE_ENC * STG1)

__global__ __launch_bounds__(256, 2) void hgemm_enc(
    const h16* __restrict__ A, const h16* __restrict__ B,
    int K, int Ntot, const float* __restrict__ bias, float* __restrict__ outf)
{
    extern __shared__ __align__(1024) char smem[];
    const uint32_t sb = smem_u32(smem);
    const int tid  = threadIdx.x;
    const int lane = tid & 31;
    const int wid  = tid >> 5;
    const int wy   = wid >> 2;
    const int wx   = wid & 3;
    const size_t bm = (size_t)blockIdx.y * 128;
    const size_t bn = (size_t)blockIdx.x * 128;

    const int lrow  = tid >> 1;
    const int lhalf = tid & 1;
    const uint32_t swr   = (uint32_t)((lrow & 7) << 4);
    const uint32_t rbase = (uint32_t)(lrow * 128);
    const char* pA = (const char*)(A + (bm + lrow) * (size_t)K);
    const char* pB = (const char*)(B + (bn + lrow) * (size_t)K);
    const int nch = K >> 6;

    auto load_stage = [&](int s, int kc) {
        uint32_t st = sb + (uint32_t)s * STG1;
        int kbyte0 = kc << 7;
        #pragma unroll
        for (int i = 0; i < 4; i++) {
            uint32_t ko = (uint32_t)(lhalf * 64 + i * 16);
            uint32_t d  = rbase + (ko ^ swr);
            cp16(st + T_A + d, pA + kbyte0 + ko);
            cp16(st + T_B + d, pB + kbyte0 + ko);
        }
        CP_COMMIT();
    };

    const int rl  = lane & 15;
    const uint32_t kbh = (uint32_t)((lane >> 4) << 4);
    uint32_t a_base[4], a_swz[4], b_base[2], b_swz[2];
    #pragma unroll
    for (int mf = 0; mf < 4; mf++) {
        int r = wy * 64 + mf * 16 + rl;
        a_base[mf] = (uint32_t)(r * 128);
        a_swz[mf]  = (uint32_t)((r & 7) << 4);
    }
    #pragma unroll
    for (int np = 0; np < 2; np++) {
        int n = wx * 32 + np * 16 + rl;
        b_base[np] = (uint32_t)(n * 128);
        b_swz[np]  = (uint32_t)((n & 7) << 4);
    }

    float acc[4][4][4];
    #pragma unroll
    for (int i = 0; i < 4; i++)
        #pragma unroll
        for (int j = 0; j < 4; j++)
            #pragma unroll
            for (int k = 0; k < 4; k++) acc[i][j][k] = 0.f;

    auto compute_stage = [&](int s) {
        uint32_t base = sb + (uint32_t)s * STG1;
        uint32_t aP = base + T_A, bP = base + T_B;
        #pragma unroll
        for (int ks = 0; ks < 4; ks++) {
            uint32_t kb = (uint32_t)(ks * 32) + kbh;
            uint32_t a_h[4][4], b_h[2][4];
            #pragma unroll
            for (int mf = 0; mf < 4; mf++)
                ldmx4(a_h[mf], aP + a_base[mf] + (kb ^ a_swz[mf]));
            #pragma unroll
            for (int np = 0; np < 2; np++)
                ldmx4(b_h[np], bP + b_base[np] + (kb ^ b_swz[np]));
            #pragma unroll
            for (int mf = 0; mf < 4; mf++)
                #pragma unroll
                for (int nf = 0; nf < 4; nf++) {
                    int p = nf >> 1, q = nf & 1;
                    mma16816_f32(acc[mf][nf], a_h[mf], b_h[p][q], b_h[p][q + 2]);
                }
        }
    };

    load_stage(0, 0);
    if (nch > 1) load_stage(1, 1);
    int sidx = 0;
    for (int kc = 0; kc < nch; kc++) {
        if (kc + 1 < nch) { CP_WAIT1(); } else { CP_WAIT0(); }
        __syncthreads();
        if (kc + 2 < nch) {
            int s2 = sidx + 2; if (s2 >= NSTAGE_ENC) s2 -= NSTAGE_ENC;
            load_stage(s2, kc + 2);
        }
        compute_stage(sidx);
        if (++sidx == NSTAGE_ENC) sidx = 0;
    }

    const int qrow = lane >> 2;
    const int c2   = 2 * (lane & 3);
    #pragma unroll
    for (int mf = 0; mf < 4; mf++) {
        size_t r0 = bm + (size_t)(wy * 64 + mf * 16 + qrow);
        #pragma unroll
        for (int nf = 0; nf < 4; nf++) {
            size_t col = bn + (size_t)(wx * 32 + nf * 8 + c2);
            float b0 = bias[col], b1 = bias[col + 1];
            #pragma unroll
            for (int sub = 0; sub < 2; sub++) {
                size_t r = r0 + sub * 8;
                float2 o;
                o.x = acc[mf][nf][sub * 2 + 0] + b0;
                o.y = acc[mf][nf][sub * 2 + 1] + b1;
                *(float2*)(outf + r * Ntot + col) = o;
            }
        }
    }
}

// ---------------------------------------------------------------------------
// Refine: u8 score scan (16 scores/lane/iter via uint4 + __vminu4 prefilter);
// candidates q <= qthr; exact fp32 recompute; low-index tie break.
// qthr widened by +1 step to absorb quantization (error <= half step each way).
// ---------------------------------------------------------------------------
#define MARGIN 8.0f

__global__ __launch_bounds__(256) void refine_kernel(float* __restrict__ labels) {
    int warp = blockIdx.x * 8 + (threadIdx.x >> 5);
    int lane = threadIdx.x & 31;
    size_t row = (size_t)warp;

    float amin   = unford((uint32_t)(g_key[row] >> 32));
    float thresh = amin + MARGIN;
    int qthr = (int)ceilf((thresh - SCQ_OFF) * SCQ_INV) + 1;   // +1 quant guard
    if (qthr > 255) qthr = 255;
    if (qthr < 0) qthr = 0;
    const uint32_t qthr4 = (uint32_t)qthr * 0x01010101u;

    const uint8_t* sr = g_sc8 + row * CC;
    float best = CUDART_INF_F;
    int bestc = 0;

    #pragma unroll
    for (int base = 0; base < CC; base += 512) {
        uint4 v = *(const uint4*)(sr + base + lane * 16);
        // per-lane min byte via packed mins
        uint32_t m = __vminu4(__vminu4(v.x, v.y), __vminu4(v.z, v.w));
        m = __vminu4(m, m >> 16);
        m = __vminu4(m, m >> 8);
        uint32_t minb = m & 0xFF;
        uint32_t mask = __ballot_sync(0xFFFFFFFFu, minb <= (uint32_t)qthr);
        while (mask) {
            int bit = __ffs(mask) - 1;
            mask &= mask - 1;
            uint4 w;
            w.x = __shfl_sync(0xFFFFFFFFu, v.x, bit);
            w.y = __shfl_sync(0xFFFFFFFFu, v.y, bit);
            w.z = __shfl_sync(0xFFFFFFFFu, v.z, bit);
            w.w = __shfl_sync(0xFFFFFFFFu, v.w, bit);
            const uint8_t* qb = (const uint8_t*)&w;
            #pragma unroll
            for (int j = 0; j < 16; j++) {
                if (qb[j] > qthr) continue;
                int c = base + bit * 16 + j;
                const h16* xh = g_x_hi + row * DD;
                const h16* xl = g_x_lo + row * DD;
                const h16* wh = g_w2t_hi + (size_t)c * DD;
                const h16* wl = g_w2t_lo + (size_t)c * DD;
                float dot = 0.f;
                #pragma unroll
                for (int jj = 0; jj < 16; jj++) {
                    int d = lane + 32 * jj;
                    float a = __half2float(xh[d]) + __half2float(xl[d]);
                    float b = __half2float(wh[d]) + __half2float(wl[d]);
                    dot = fmaf(a, b, dot);
                }
                #pragma unroll
                for (int off = 16; off > 0; off >>= 1)
                    dot += __shfl_down_sync(0xFFFFFFFFu, dot, off);
                if (lane == 0) {
                    float sc = g_csq[c] - 2.0f * dot;
                    if (sc < best || (sc == best && c < bestc)) { best = sc; bestc = c; }
                }
            }
        }
    }
    if (lane == 0) labels[row] = (float)bestc;
}

// ---------------------------------------------------------------------------
// W2^T precompute + fused csq (R10-proven).
// ---------------------------------------------------------------------------
__global__ __launch_bounds__(256) void w2t_kernel(const float* __restrict__ projw,
                                                  const float* __restrict__ cb) {
    __shared__ __align__(16) float As[8][128];
    __shared__ __align__(16) float Bs[8][128];
    __shared__ float cred[2][128];

    int tid = threadIdx.x;
    int c0 = blockIdx.x * 128;
    int d0 = blockIdx.y * 128;
    int lr = tid >> 5, lc = (tid & 31) * 4;
    int ty = tid >> 4, tx = tid & 15;

    int qcol = tid & 127;
    int qgrp = tid >> 7;
    float csum = 0.f;

    float acc[8][8];
    #pragma unroll
    for (int i = 0; i < 8; i++)
        #pragma unroll
        for (int j = 0; j < 8; j++) acc[i][j] = 0.f;

    for (int k0 = 0; k0 < QQ; k0 += 8) {
        *(float4*)&As[lr][lc] = *(const float4*)(cb + (size_t)(k0 + lr) * CC + c0 + lc);
        *(float4*)&Bs[lr][lc] = *(const float4*)(projw + (size_t)(k0 + lr) * DD + d0 + lc);
        __syncthreads();

        if (d0 == 0) {
            #pragma unroll
            for (int r = 0; r < 4; r++) {
                float v = As[qgrp * 4 + r][qcol];
                csum = fmaf(v, v, csum);
            }
        }

        #pragma unroll
        for (int k = 0; k < 8; k++) {
            float ar[8], br[8];
            float4 a0 = *(const float4*)&As[k][ty * 8];
            float4 a1 = *(const float4*)&As[k][ty * 8 + 4];
            float4 b0 = *(const float4*)&Bs[k][tx * 8];
            float4 b1 = *(const float4*)&Bs[k][tx * 8 + 4];
            ar[0]=a0.x; ar[1]=a0.y; ar[2]=a0.z; ar[3]=a0.w;
            ar[4]=a1.x; ar[5]=a1.y; ar[6]=a1.z; ar[7]=a1.w;
            br[0]=b0.x; br[1]=b0.y; br[2]=b0.z; br[3]=b0.w;
            br[4]=b1.x; br[5]=b1.y; br[6]=b1.z; br[7]=b1.w;
            #pragma unroll
            for (int i = 0; i < 8; i++)
                #pragma unroll
                for (int j = 0; j < 8; j++)
                    acc[i][j] = fmaf(ar[i], br[j], acc[i][j]);
        }
        __syncthreads();
    }

    if (d0 == 0) {
        cred[qgrp][qcol] = csum;
        __syncthreads();
        if (tid < 128) g_csq[c0 + tid] = cred[0][tid] + cred[1][tid];
    }

    #pragma unroll
    for (int i = 0; i < 8; i++) {
        size_t rowo = (size_t)(c0 + ty * 8 + i) * DD + d0 + tx * 8;
        #pragma unroll
        for (int j = 0; j < 8; j++) {
            float v = acc[i][j];
            h16 h = __float2half(v);
            g_w2t_hi[rowo + j] = h;
            g_w2t_lo[rowo + j] = __float2half(v - __half2float(h));
        }
    }
}

// ---------------------------------------------------------------------------
// LayerNorm over D=512, writes fp16 hi/lo split + inits g_key for its row.
// ---------------------------------------------------------------------------
__global__ __launch_bounds__(256) void ln_kernel(const float* __restrict__ x,
                                                 const float* __restrict__ gamma,
                                                 const float* __restrict__ beta) {
    int r = blockIdx.x;
    const float* xr = x + (size_t)r * DD;
    int t = threadIdx.x;

    if (t == 0) g_key[r] = 0xFFFFFFFFFFFFFFFFull;

    float v0 = xr[t], v1 = xr[t + 256];
    float s = v0 + v1, ss = v0 * v0 + v1 * v1;
    #pragma unroll
    for (int off = 16; off > 0; off >>= 1) {
        s  += __shfl_down_sync(0xFFFFFFFFu, s,  off);
        ss += __shfl_down_sync(0xFFFFFFFFu, ss, off);
    }
    __shared__ float sh_s[8], sh_ss[8];
    int w = t >> 5, l = t & 31;
    if (l == 0) { sh_s[w] = s; sh_ss[w] = ss; }
    __syncthreads();
    if (t == 0) {
        float S = 0.f, SS = 0.f;
        #pragma unroll
        for (int i = 0; i < 8; i++) { S += sh_s[i]; SS += sh_ss[i]; }
        sh_s[0]  = S * (1.0f / DD);
        sh_ss[0] = SS * (1.0f / DD);
    }
    __syncthreads();
    float mu = sh_s[0];
    float rs = rsqrtf(sh_ss[0] - mu * mu + 1e-5f);

    float y0 = (v0 - mu) * rs * gamma[t]       + beta[t];
    float y1 = (v1 - mu) * rs * gamma[t + 256] + beta[t + 256];

    size_t base = (size_t)r * DD;
    h16 h0 = __float2half(y0), h1 = __float2half(y1);
    g_x_hi[base + t]       = h0;
    g_x_hi[base + t + 256] = h1;
    g_x_lo[base + t]       = __float2half(y0 - __half2float(h0));
    g_x_lo[base + t + 256] = __float2half(y1 - __half2float(h1));
}

// ---------------------------------------------------------------------------
__global__ __launch_bounds__(256) void split_hi_kernel(const float* __restrict__ src,
                                                       h16* __restrict__ hi, int n) {
    int i = blockIdx.x * 256 + threadIdx.x;
    if (i < n) hi[i] = __float2half(src[i]);
}

// ---------------------------------------------------------------------------
extern "C" void kernel_launch(void* const* d_in, const int* in_sizes, int n_in,
                              void* d_out, int out_size) {
    const float* x     = (const float*)d_in[0];
    const float* gamma = (const float*)d_in[1];
    const float* beta  = (const float*)d_in[2];
    const float* projw = (const float*)d_in[3];
    const float* cb    = (const float*)d_in[4];
    const float* encw  = (const float*)d_in[5];
    const float* encb  = (const float*)d_in[6];

    float* out     = (float*)d_out;
    float* enc_out = out;                               // (M, Q) fp32
    float* labels  = out + ((size_t)out_size - MM);     // (M,) as fp32

    h16 *xh, *w2h, *ewh;
    cudaGetSymbolAddress((void**)&xh, g_x_hi);
    cudaGetSymbolAddress((void**)&w2h, g_w2t_hi);
    cudaGetSymbolAddress((void**)&ewh, g_ew_hi);

    cudaFuncSetAttribute(hgemm_enc, cudaFuncAttributeMaxDynamicSharedMemorySize,
                         SMEM_ENC);
    cudaFuncSetAttribute(hgemm_screen, cudaFuncAttributeMaxDynamicSharedMemorySize,
                         SMEM_SCREEN);

    // Launch order keeps hgemm_screen in the ncu capture slot (4th launch).
    // 1) LayerNorm -> fp16 split (+ g_key init)
    ln_kernel<<<MM, 256>>>(x, gamma, beta);

    // 2) fused codebook matrix W2^T (+ csq in d0==0 blocks)
    w2t_kernel<<<dim3(CC / 128, DD / 128), 256>>>(projw, cb);

    // 3) enc weight split
    split_hi_kernel<<<(QQ * DD + 255) / 256, 256>>>(encw, ewh, QQ * DD);

    // 4) label screen (R11 mainloop, u8 score epilogue)
    dim3 gridx(CC / 128, MM / 128);
    hgemm_screen<<<gridx, 256, SMEM_SCREEN>>>(xh, w2h, DD);

    // 5) encoder GEMM (fp32-accum 1-pass, 3-stage)
    dim3 grid12(QQ / 128, MM / 128);
    hgemm_enc<<<grid12, 256, SMEM_ENC>>>(xh, ewh, DD, QQ, encb, enc_out);

    // 6) exact refinement (u8 scan) -> labels
    refine_kernel<<<MM / 8, 256>>>(labels);

    (void)in_sizes; (void)n_in;
}

// round 15
// speedup vs baseline: 1.3493x; 1.0843x over previous
#include <cuda_runtime.h>
#include <cuda_fp16.h>
#include <math_constants.h>
#include <cstdint>

// Problem constants
#define BB 8
#define TT 8192
#define DD 512
#define QQ 1024
#define CC 4096
#define MM (BB * TT)   // 65536
#define NGRP 128       // 32-col score groups per row (CC/32)

typedef __half h16;

// ---------------------------------------------------------------------------
// Scratch (__device__ globals; allocation-free rule)
// ---------------------------------------------------------------------------
__device__ __align__(16) h16 g_x_hi[(size_t)MM * DD];
__device__ __align__(16) h16 g_x_lo[(size_t)MM * DD];
__device__ __align__(16) h16 g_w2t_hi[(size_t)CC * DD];   // W2^T [C][D]
__device__ __align__(16) h16 g_w2t_lo[(size_t)CC * DD];
__device__ __align__(16) h16 g_ew_hi[(size_t)QQ * DD];
__device__ __align__(16) h16 g_sc[(size_t)MM * CC];       // fp16 scores (512 MB)
__device__ __align__(16) h16 g_gmin[(size_t)MM * NGRP];   // per-group mins (16.8 MB)
__device__ float g_csq[CC];

// ---------------------------------------------------------------------------
// PTX helpers
// ---------------------------------------------------------------------------
__device__ __forceinline__ uint32_t smem_u32(const void* p) {
    uint32_t a;
    asm("{ .reg .u64 t; cvta.to.shared.u64 t, %1; cvt.u32.u64 %0, t; }"
        : "=r"(a) : "l"(p));
    return a;
}
__device__ __forceinline__ void cp16(uint32_t dst, const void* src) {
    asm volatile("cp.async.cg.shared.global [%0], [%1], 16;" :: "r"(dst), "l"(src));
}
#define CP_COMMIT() asm volatile("cp.async.commit_group;")
#define CP_WAIT1()  asm volatile("cp.async.wait_group 1;")
#define CP_WAIT0()  asm volatile("cp.async.wait_group 0;")

__device__ __forceinline__ void ldmx4(uint32_t* r, uint32_t addr) {
    asm volatile("ldmatrix.sync.aligned.m8n8.x4.shared.b16 {%0,%1,%2,%3}, [%4];"
                 : "=r"(r[0]), "=r"(r[1]), "=r"(r[2]), "=r"(r[3]) : "r"(addr));
}
__device__ __forceinline__ void mma16816_f32(float* d, const uint32_t* a,
                                             uint32_t b0, uint32_t b1) {
    asm volatile("mma.sync.aligned.m16n8k16.row.col.f32.f16.f16.f32 "
                 "{%0,%1,%2,%3}, {%4,%5,%6,%7}, {%8,%9}, {%0,%1,%2,%3};"
                 : "+f"(d[0]), "+f"(d[1]), "+f"(d[2]), "+f"(d[3])
                 : "r"(a[0]), "r"(a[1]), "r"(a[2]), "r"(a[3]), "r"(b0), "r"(b1));
}
__device__ __forceinline__ void mma16816_f16(uint32_t* d, const uint32_t* a,
                                             uint32_t b0, uint32_t b1) {
    asm volatile("mma.sync.aligned.m16n8k16.row.col.f16.f16.f16.f16 "
                 "{%0,%1}, {%2,%3,%4,%5}, {%6,%7}, {%0,%1};"
                 : "+r"(d[0]), "+r"(d[1])
                 : "r"(a[0]), "r"(a[1]), "r"(a[2]), "r"(a[3]), "r"(b0), "r"(b1));
}

// ---------------------------------------------------------------------------
// Screen GEMM (R11-proven mainloop): BM=BN=128, BK=64, f16 accum, 1-pass hi,
// 256 thr (2x4 warps), NSTAGE=2 -> 64KB smem -> 3 CTAs/SM.
// Epilogue: fp16 score store + per-(row, 32-col group) fp16 min store
// (plain stores, NO atomics).
// ---------------------------------------------------------------------------
#define T_A    0
#define T_B    16384
#define STG1   32768
#define SMEM_SCREEN (2 * STG1)

__global__ __launch_bounds__(256, 3) void hgemm_screen(
    const h16* __restrict__ A, const h16* __restrict__ B, int K)
{
    extern __shared__ __align__(1024) char smem[];
    const uint32_t sb = smem_u32(smem);
    const int tid  = threadIdx.x;
    const int lane = tid & 31;
    const int wid  = tid >> 5;
    const int wy   = wid >> 2;
    const int wx   = wid & 3;
    const size_t bm = (size_t)blockIdx.y * 128;
    const size_t bn = (size_t)blockIdx.x * 128;

    uint32_t acc[4][4][2];
    #pragma unroll
    for (int i = 0; i < 4; i++)
        #pragma unroll
        for (int j = 0; j < 4; j++) { acc[i][j][0] = 0u; acc[i][j][1] = 0u; }

    const int lrow  = tid >> 1;
    const int lhalf = tid & 1;
    const uint32_t swr   = (uint32_t)((lrow & 7) << 4);
    const uint32_t rbase = (uint32_t)(lrow * 128);
    const char* pA = (const char*)(A + (bm + lrow) * (size_t)K);
    const char* pB = (const char*)(B + (bn + lrow) * (size_t)K);
    const int nch = K >> 6;

    auto load_stage = [&](int s, int kc) {
        uint32_t st = sb + (uint32_t)s * STG1;
        int kbyte0 = kc << 7;
        #pragma unroll
        for (int i = 0; i < 4; i++) {
            uint32_t ko = (uint32_t)(lhalf * 64 + i * 16);
            uint32_t d  = rbase + (ko ^ swr);
            cp16(st + T_A + d, pA + kbyte0 + ko);
            cp16(st + T_B + d, pB + kbyte0 + ko);
        }
        CP_COMMIT();
    };

    const int rl  = lane & 15;
    const uint32_t kbh = (uint32_t)((lane >> 4) << 4);
    uint32_t a_base[4], a_swz[4], b_base[2], b_swz[2];
    #pragma unroll
    for (int mf = 0; mf < 4; mf++) {
        int r = wy * 64 + mf * 16 + rl;
        a_base[mf] = (uint32_t)(r * 128);
        a_swz[mf]  = (uint32_t)((r & 7) << 4);
    }
    #pragma unroll
    for (int np = 0; np < 2; np++) {
        int n = wx * 32 + np * 16 + rl;
        b_base[np] = (uint32_t)(n * 128);
        b_swz[np]  = (uint32_t)((n & 7) << 4);
    }

    auto compute_stage = [&](int s) {
        uint32_t base = sb + (uint32_t)s * STG1;
        uint32_t aP = base + T_A, bP = base + T_B;
        #pragma unroll
        for (int ks = 0; ks < 4; ks++) {
            uint32_t kb = (uint32_t)(ks * 32) + kbh;
            uint32_t a_h[4][4], b_h[2][4];
            #pragma unroll
            for (int mf = 0; mf < 4; mf++)
                ldmx4(a_h[mf], aP + a_base[mf] + (kb ^ a_swz[mf]));
            #pragma unroll
            for (int np = 0; np < 2; np++)
                ldmx4(b_h[np], bP + b_base[np] + (kb ^ b_swz[np]));
            #pragma unroll
            for (int mf = 0; mf < 4; mf++)
                #pragma unroll
                for (int nf = 0; nf < 4; nf++) {
                    int p = nf >> 1, q = nf & 1;
                    mma16816_f16(acc[mf][nf], a_h[mf], b_h[p][q], b_h[p][q + 2]);
                }
        }
    };

    // 2-stage pipelined main loop (R11 structure)
    load_stage(0, 0);
    for (int kc = 0; kc < nch; kc++) {
        if (kc + 1 < nch) load_stage((kc + 1) & 1, kc + 1);
        if (kc + 1 < nch) { CP_WAIT1(); } else { CP_WAIT0(); }
        __syncthreads();
        compute_stage(kc & 1);
        __syncthreads();
    }

    // epilogue: fp16 score store + group-min store (no atomics)
    const int qrow = lane >> 2;
    const int c2   = 2 * (lane & 3);
    const int grp  = (int)blockIdx.x * 4 + wx;   // 32-col group index
    #pragma unroll
    for (int mf = 0; mf < 4; mf++) {
        #pragma unroll
        for (int sub = 0; sub < 2; sub++) {
            size_t row = bm + (size_t)(wy * 64 + mf * 16 + sub * 8 + qrow);
            float mn = CUDART_INF_F;
            #pragma unroll
            for (int nf = 0; nf < 4; nf++) {
                int col = (int)bn + wx * 32 + nf * 8 + c2;
                __half2 d2 = *(__half2*)&acc[mf][nf][sub];
                float s0 = g_csq[col]     - 2.0f * __half2float(__low2half(d2));
                float s1 = g_csq[col + 1] - 2.0f * __half2float(__high2half(d2));
                __half2 hp = __floats2half2_rn(s0, s1);
                uint32_t u; *(__half2*)&u = hp;
                __stcs((uint32_t*)(g_sc + row * CC + col), u);
                mn = fminf(mn, fminf(s0, s1));
            }
            mn = fminf(mn, __shfl_down_sync(0xFFFFFFFFu, mn, 2));
            mn = fminf(mn, __shfl_down_sync(0xFFFFFFFFu, mn, 1));
            if ((lane & 3) == 0)
                g_gmin[row * NGRP + grp] = __float2half(mn);
        }
    }
}

// ---------------------------------------------------------------------------
// Encoder GEMM (unchanged, R10/R11-proven): BM=BN=128, BK=64, fp32 accum,
// NSTAGE=3, 2 CTAs/SM.
// ---------------------------------------------------------------------------
#define NSTAGE_ENC 3
#define SMEM_ENC (NSTAGE_ENC * STG1)

__global__ __launch_bounds__(256, 2) void hgemm_enc(
    const h16* __restrict__ A, const h16* __restrict__ B,
    int K, int Ntot, const float* __restrict__ bias, float* __restrict__ outf)
{
    extern __shared__ __align__(1024) char smem[];
    const uint32_t sb = smem_u32(smem);
    const int tid  = threadIdx.x;
    const int lane = tid & 31;
    const int wid  = tid >> 5;
    const int wy   = wid >> 2;
    const int wx   = wid & 3;
    const size_t bm = (size_t)blockIdx.y * 128;
    const size_t bn = (size_t)blockIdx.x * 128;

    const int lrow  = tid >> 1;
    const int lhalf = tid & 1;
    const uint32_t swr   = (uint32_t)((lrow & 7) << 4);
    const uint32_t rbase = (uint32_t)(lrow * 128);
    const char* pA = (const char*)(A + (bm + lrow) * (size_t)K);
    const char* pB = (const char*)(B + (bn + lrow) * (size_t)K);
    const int nch = K >> 6;

    auto load_stage = [&](int s, int kc) {
        uint32_t st = sb + (uint32_t)s * STG1;
        int kbyte0 = kc << 7;
        #pragma unroll
        for (int i = 0; i < 4; i++) {
            uint32_t ko = (uint32_t)(lhalf * 64 + i * 16);
            uint32_t d  = rbase + (ko ^ swr);
            cp16(st + T_A + d, pA + kbyte0 + ko);
            cp16(st + T_B + d, pB + kbyte0 + ko);
        }
        CP_COMMIT();
    };

    const int rl  = lane & 15;
    const uint32_t kbh = (uint32_t)((lane >> 4) << 4);
    uint32_t a_base[4], a_swz[4], b_base[2], b_swz[2];
    #pragma unroll
    for (int mf = 0; mf < 4; mf++) {
        int r = wy * 64 + mf * 16 + rl;
        a_base[mf] = (uint32_t)(r * 128);
        a_swz[mf]  = (uint32_t)((r & 7) << 4);
    }
    #pragma unroll
    for (int np = 0; np < 2; np++) {
        int n = wx * 32 + np * 16 + rl;
        b_base[np] = (uint32_t)(n * 128);
        b_swz[np]  = (uint32_t)((n & 7) << 4);
    }

    float acc[4][4][4];
    #pragma unroll
    for (int i = 0; i < 4; i++)
        #pragma unroll
        for (int j = 0; j < 4; j++)
            #pragma unroll
            for (int k = 0; k < 4; k++) acc[i][j][k] = 0.f;

    auto compute_stage = [&](int s) {
        uint32_t base = sb + (uint32_t)s * STG1;
        uint32_t aP = base + T_A, bP = base + T_B;
        #pragma unroll
        for (int ks = 0; ks < 4; ks++) {
            uint32_t kb = (uint32_t)(ks * 32) + kbh;
            uint32_t a_h[4][4], b_h[2][4];
            #pragma unroll
            for (int mf = 0; mf < 4; mf++)
                ldmx4(a_h[mf], aP + a_base[mf] + (kb ^ a_swz[mf]));
            #pragma unroll
            for (int np = 0; np < 2; np++)
                ldmx4(b_h[np], bP + b_base[np] + (kb ^ b_swz[np]));
            #pragma unroll
            for (int mf = 0; mf < 4; mf++)
                #pragma unroll
                for (int nf = 0; nf < 4; nf++) {
                    int p = nf >> 1, q = nf & 1;
                    mma16816_f32(acc[mf][nf], a_h[mf], b_h[p][q], b_h[p][q + 2]);
                }
        }
    };

    load_stage(0, 0);
    if (nch > 1) load_stage(1, 1);
    int sidx = 0;
    for (int kc = 0; kc < nch; kc++) {
        if (kc + 1 < nch) { CP_WAIT1(); } else { CP_WAIT0(); }
        __syncthreads();
        if (kc + 2 < nch) {
            int s2 = sidx + 2; if (s2 >= NSTAGE_ENC) s2 -= NSTAGE_ENC;
            load_stage(s2, kc + 2);
        }
        compute_stage(sidx);
        if (++sidx == NSTAGE_ENC) sidx = 0;
    }

    const int qrow = lane >> 2;
    const int c2   = 2 * (lane & 3);
    #pragma unroll
    for (int mf = 0; mf < 4; mf++) {
        size_t r0 = bm + (size_t)(wy * 64 + mf * 16 + qrow);
        #pragma unroll
        for (int nf = 0; nf < 4; nf++) {
            size_t col = bn + (size_t)(wx * 32 + nf * 8 + c2);
            float b0 = bias[col], b1 = bias[col + 1];
            #pragma unroll
            for (int sub = 0; sub < 2; sub++) {
                size_t r = r0 + sub * 8;
                float2 o;
                o.x = acc[mf][nf][sub * 2 + 0] + b0;
                o.y = acc[mf][nf][sub * 2 + 1] + b1;
                *(float2*)(outf + r * Ntot + col) = o;
            }
        }
    }
}

// ---------------------------------------------------------------------------
// Refine: hierarchical. One warp per row.
// 1) read 128 group-mins (256B), compute row min, ballot candidate groups
//    (gmin <= rowmin + MARGIN + 1; the +1 covers fp16 rounding of mins).
// 2) scan only candidate groups' scores (32 fp16 per group, one per lane).
// 3) exact fp32 recompute of score-candidates; lowest-index tie break.
// ---------------------------------------------------------------------------
#define MARGIN 8.0f

__global__ __launch_bounds__(256) void refine_kernel(float* __restrict__ labels) {
    int warp = blockIdx.x * 8 + (threadIdx.x >> 5);
    int lane = threadIdx.x & 31;
    size_t row = (size_t)warp;

    // 1) group mins: lane l holds groups 4l..4l+3
    const h16* gm = g_gmin + row * NGRP;
    uint2 gv = *(const uint2*)(gm + lane * 4);
    __half2 gp0 = *(__half2*)&gv.x;
    __half2 gp1 = *(__half2*)&gv.y;
    float m0 = __half2float(__low2half(gp0));
    float m1 = __half2float(__high2half(gp0));
    float m2 = __half2float(__low2half(gp1));
    float m3 = __half2float(__high2half(gp1));
    float lmin = fminf(fminf(m0, m1), fminf(m2, m3));
    float rowmin = lmin;
    #pragma unroll
    for (int off = 16; off > 0; off >>= 1)
        rowmin = fminf(rowmin, __shfl_xor_sync(0xFFFFFFFFu, rowmin, off));
    const float thr = rowmin + MARGIN + 1.0f;

    float best = CUDART_INF_F;
    int bestc = 0;
    const h16* sr = g_sc + row * CC;

    float gmins[4] = {m0, m1, m2, m3};
    #pragma unroll
    for (int j = 0; j < 4; j++) {
        uint32_t gmask = __ballot_sync(0xFFFFFFFFu, gmins[j] <= thr);
        while (gmask) {
            int bit = __ffs(gmask) - 1;
            gmask &= gmask - 1;
            int g = bit * 4 + j;
            // 2) scan this group's 32 scores, one per lane
            float s = __half2float(sr[g * 32 + lane]);
            uint32_t cmask = __ballot_sync(0xFFFFFFFFu, s <= thr);
            while (cmask) {
                int cbit = __ffs(cmask) - 1;
                cmask &= cmask - 1;
                int c = g * 32 + cbit;
                // 3) exact warp-cooperative fp32 dot over D=512
                const h16* xh = g_x_hi + row * DD;
                const h16* xl = g_x_lo + row * DD;
                const h16* wh = g_w2t_hi + (size_t)c * DD;
                const h16* wl = g_w2t_lo + (size_t)c * DD;
                float dot = 0.f;
                #pragma unroll
                for (int jj = 0; jj < 16; jj++) {
                    int d = lane + 32 * jj;
                    float a = __half2float(xh[d]) + __half2float(xl[d]);
                    float b = __half2float(wh[d]) + __half2float(wl[d]);
                    dot = fmaf(a, b, dot);
                }
                #pragma unroll
                for (int off = 16; off > 0; off >>= 1)
                    dot += __shfl_down_sync(0xFFFFFFFFu, dot, off);
                if (lane == 0) {
                    float sc = g_csq[c] - 2.0f * dot;
                    if (sc < best || (sc == best && c < bestc)) { best = sc; bestc = c; }
                }
            }
        }
    }
    if (lane == 0) labels[row] = (float)bestc;
}

// ---------------------------------------------------------------------------
// W2^T precompute + fused csq (R10-proven).
// ---------------------------------------------------------------------------
__global__ __launch_bounds__(256) void w2t_kernel(const float* __restrict__ projw,
                                                  const float* __restrict__ cb) {
    __shared__ __align__(16) float As[8][128];
    __shared__ __align__(16) float Bs[8][128];
    __shared__ float cred[2][128];

    int tid = threadIdx.x;
    int c0 = blockIdx.x * 128;
    int d0 = blockIdx.y * 128;
    int lr = tid >> 5, lc = (tid & 31) * 4;
    int ty = tid >> 4, tx = tid & 15;

    int qcol = tid & 127;
    int qgrp = tid >> 7;
    float csum = 0.f;

    float acc[8][8];
    #pragma unroll
    for (int i = 0; i < 8; i++)
        #pragma unroll
        for (int j = 0; j < 8; j++) acc[i][j] = 0.f;

    for (int k0 = 0; k0 < QQ; k0 += 8) {
        *(float4*)&As[lr][lc] = *(const float4*)(cb + (size_t)(k0 + lr) * CC + c0 + lc);
        *(float4*)&Bs[lr][lc] = *(const float4*)(projw + (size_t)(k0 + lr) * DD + d0 + lc);
        __syncthreads();

        if (d0 == 0) {
            #pragma unroll
            for (int r = 0; r < 4; r++) {
                float v = As[qgrp * 4 + r][qcol];
                csum = fmaf(v, v, csum);
            }
        }

        #pragma unroll
        for (int k = 0; k < 8; k++) {
            float ar[8], br[8];
            float4 a0 = *(const float4*)&As[k][ty * 8];
            float4 a1 = *(const float4*)&As[k][ty * 8 + 4];
            float4 b0 = *(const float4*)&Bs[k][tx * 8];
            float4 b1 = *(const float4*)&Bs[k][tx * 8 + 4];
            ar[0]=a0.x; ar[1]=a0.y; ar[2]=a0.z; ar[3]=a0.w;
            ar[4]=a1.x; ar[5]=a1.y; ar[6]=a1.z; ar[7]=a1.w;
            br[0]=b0.x; br[1]=b0.y; br[2]=b0.z; br[3]=b0.w;
            br[4]=b1.x; br[5]=b1.y; br[6]=b1.z; br[7]=b1.w;
            #pragma unroll
            for (int i = 0; i < 8; i++)
                #pragma unroll
                for (int j = 0; j < 8; j++)
                    acc[i][j] = fmaf(ar[i], br[j], acc[i][j]);
        }
        __syncthreads();
    }

    if (d0 == 0) {
        cred[qgrp][qcol] = csum;
        __syncthreads();
        if (tid < 128) g_csq[c0 + tid] = cred[0][tid] + cred[1][tid];
    }

    #pragma unroll
    for (int i = 0; i < 8; i++) {
        size_t rowo = (size_t)(c0 + ty * 8 + i) * DD + d0 + tx * 8;
        #pragma unroll
        for (int j = 0; j < 8; j++) {
            float v = acc[i][j];
            h16 h = __float2half(v);
            g_w2t_hi[rowo + j] = h;
            g_w2t_lo[rowo + j] = __float2half(v - __half2float(h));
        }
    }
}

// ---------------------------------------------------------------------------
// LayerNorm over D=512, writes fp16 hi/lo split.
// ---------------------------------------------------------------------------
__global__ __launch_bounds__(256) void ln_kernel(const float* __restrict__ x,
                                                 const float* __restrict__ gamma,
                                                 const float* __restrict__ beta) {
    int r = blockIdx.x;
    const float* xr = x + (size_t)r * DD;
    int t = threadIdx.x;

    float v0 = xr[t], v1 = xr[t + 256];
    float s = v0 + v1, ss = v0 * v0 + v1 * v1;
    #pragma unroll
    for (int off = 16; off > 0; off >>= 1) {
        s  += __shfl_down_sync(0xFFFFFFFFu, s,  off);
        ss += __shfl_down_sync(0xFFFFFFFFu, ss, off);
    }
    __shared__ float sh_s[8], sh_ss[8];
    int w = t >> 5, l = t & 31;
    if (l == 0) { sh_s[w] = s; sh_ss[w] = ss; }
    __syncthreads();
    if (t == 0) {
        float S = 0.f, SS = 0.f;
        #pragma unroll
        for (int i = 0; i < 8; i++) { S += sh_s[i]; SS += sh_ss[i]; }
        sh_s[0]  = S * (1.0f / DD);
        sh_ss[0] = SS * (1.0f / DD);
    }
    __syncthreads();
    float mu = sh_s[0];
    float rs = rsqrtf(sh_ss[0] - mu * mu + 1e-5f);

    float y0 = (v0 - mu) * rs * gamma[t]       + beta[t];
    float y1 = (v1 - mu) * rs * gamma[t + 256] + beta[t + 256];

    size_t base = (size_t)r * DD;
    h16 h0 = __float2half(y0), h1 = __float2half(y1);
    g_x_hi[base + t]       = h0;
    g_x_hi[base + t + 256] = h1;
    g_x_lo[base + t]       = __float2half(y0 - __half2float(h0));
    g_x_lo[base + t + 256] = __float2half(y1 - __half2float(h1));
}

// ---------------------------------------------------------------------------
__global__ __launch_bounds__(256) void split_hi_kernel(const float* __restrict__ src,
                                                       h16* __restrict__ hi, int n) {
    int i = blockIdx.x * 256 + threadIdx.x;
    if (i < n) hi[i] = __float2half(src[i]);
}

// ---------------------------------------------------------------------------
extern "C" void kernel_launch(void* const* d_in, const int* in_sizes, int n_in,
                              void* d_out, int out_size) {
    const float* x     = (const float*)d_in[0];
    const float* gamma = (const float*)d_in[1];
    const float* beta  = (const float*)d_in[2];
    const float* projw = (const float*)d_in[3];
    const float* cb    = (const float*)d_in[4];
    const float* encw  = (const float*)d_in[5];
    const float* encb  = (const float*)d_in[6];

    float* out     = (float*)d_out;
    float* enc_out = out;                               // (M, Q) fp32
    float* labels  = out + ((size_t)out_size - MM);     // (M,) as fp32

    h16 *xh, *w2h, *ewh;
    cudaGetSymbolAddress((void**)&xh, g_x_hi);
    cudaGetSymbolAddress((void**)&w2h, g_w2t_hi);
    cudaGetSymbolAddress((void**)&ewh, g_ew_hi);

    cudaFuncSetAttribute(hgemm_enc, cudaFuncAttributeMaxDynamicSharedMemorySize,
                         SMEM_ENC);
    cudaFuncSetAttribute(hgemm_screen, cudaFuncAttributeMaxDynamicSharedMemorySize,
                         SMEM_SCREEN);

    // Launch order keeps hgemm_screen in the ncu capture slot (4th launch).
    // 1) LayerNorm -> fp16 split
    ln_kernel<<<MM, 256>>>(x, gamma, beta);

    // 2) fused codebook matrix W2^T (+ csq in d0==0 blocks)
    w2t_kernel<<<dim3(CC / 128, DD / 128), 256>>>(projw, cb);

    // 3) enc weight split
    split_hi_kernel<<<(QQ * DD + 255) / 256, 256>>>(encw, ewh, QQ * DD);

    // 4) label screen (R11 mainloop, group-min epilogue, no atomics)
    dim3 gridx(CC / 128, MM / 128);
    hgemm_screen<<<gridx, 256, SMEM_SCREEN>>>(xh, w2h, DD);

    // 5) encoder GEMM (fp32-accum 1-pass, 3-stage)
    dim3 grid12(QQ / 128, MM / 128);
    hgemm_enc<<<grid12, 256, SMEM_ENC>>>(xh, ewh, DD, QQ, encb, enc_out);

    // 6) hierarchical refine -> labels
    refine_kernel<<<MM / 8, 256>>>(labels);

    (void)in_sizes; (void)n_in;
}